// round 16
// baseline (speedup 1.0000x reference)
#include <cuda_runtime.h>
#include <cuda_bf16.h>
#include <cuda_fp16.h>
#include <cstdint>
#include <math.h>

// Problem constants
#define BATCH  2
#define SEQ    2048
#define DMODEL 4096
#define NH     32
#define NKV    8
#define HDIM   128
#define MTOT   (BATCH*SEQ)
#define QKVN   6144
#define SCALE  0.08838834764831843f   // 1/sqrt(128)

// GEMM tiling: 128x128 CTA tile, 4 warps (2x2), warp tile 64x64, GKC=64, persistent CTAs
#define GMT 128
#define GNT 128
#define GKC 64
#define OPB (128*GKC*2)                // 16KB per operand tile
#define PERSIST_CTAS 296               // 148 SMs x 2 CTAs/SM

// flash tiling (R14 validated)
#define FBQ 64
#define FBK 64
#define FLASH_SMEM 65536

// -------- scratch --------
__device__ __align__(16) __half g_hid_hi [(size_t)MTOT*DMODEL];
__device__ __align__(16) __half g_hid_lo [(size_t)MTOT*DMODEL];
__device__ __align__(16) __half g_wqkv_hi[(size_t)QKVN*DMODEL];
__device__ __align__(16) __half g_wo_hi  [(size_t)DMODEL*DMODEL];
__device__ __align__(16) float g_qkv [(size_t)MTOT*QKVN];
__device__ __align__(16) __half g_q_hi [(size_t)MTOT*NH*HDIM];
__device__ __align__(16) __half g_q_lo [(size_t)MTOT*NH*HDIM];
__device__ __align__(16) __half g_k_hi [(size_t)MTOT*NKV*HDIM];
__device__ __align__(16) __half g_vt_hi[(size_t)BATCH*NKV*HDIM*SEQ];
__device__ __align__(16) __half g_ao_hi[(size_t)MTOT*DMODEL];
__device__ float g_bias[QKVN];
__device__ float g_cos[SEQ*64];
__device__ float g_sin[SEQ*64];

// ======================= helpers =======================
__device__ __forceinline__ uint32_t smem_u32(const void* p) {
    uint32_t a;
    asm("{ .reg .u64 t; cvta.to.shared.u64 t, %1; cvt.u32.u64 %0, t; }" : "=r"(a) : "l"(p));
    return a;
}
__device__ __forceinline__ void cp16(uint32_t s, const void* g) {
    asm volatile("cp.async.cg.shared.global [%0], [%1], 16;" :: "r"(s), "l"(g));
}
#define CP_COMMIT()  asm volatile("cp.async.commit_group;" ::: "memory")
#define CP_WAIT(n)   asm volatile("cp.async.wait_group %0;" :: "n"(n) : "memory")

__device__ __forceinline__ void ldsm4(uint32_t& r0, uint32_t& r1, uint32_t& r2, uint32_t& r3,
                                      uint32_t a) {
    asm volatile("ldmatrix.sync.aligned.m8n8.x4.shared.b16 {%0,%1,%2,%3}, [%4];"
        : "=r"(r0), "=r"(r1), "=r"(r2), "=r"(r3) : "r"(a));
}
__device__ __forceinline__ void mma_fp16(float* c, const uint32_t* a, const uint32_t* b) {
    asm volatile("mma.sync.aligned.m16n8k16.row.col.f32.f16.f16.f32 "
        "{%0,%1,%2,%3}, {%4,%5,%6,%7}, {%8,%9}, {%0,%1,%2,%3};"
        : "+f"(c[0]), "+f"(c[1]), "+f"(c[2]), "+f"(c[3])
        : "r"(a[0]), "r"(a[1]), "r"(a[2]), "r"(a[3]), "r"(b[0]), "r"(b[1]));
}
__device__ __forceinline__ void split2h(float x, unsigned short& h, unsigned short& l) {
    __half hb = __float2half_rn(x);
    float hf = __half2float(hb);
    __half lb = __float2half_rn(x - hf);
    h = __half_as_ushort(hb);
    l = __half_as_ushort(lb);
}
__device__ __forceinline__ uint32_t pack2h(float x0, float x1) {
    return (uint32_t)__half_as_ushort(__float2half_rn(x0)) |
           ((uint32_t)__half_as_ushort(__float2half_rn(x1)) << 16);
}
#define ROFF(r,c) ((uint32_t)((r)*128 + (((c) ^ ((r)&7))<<4)))
#define QOFF(r,c) ((uint32_t)((r)*256 + (((c) ^ ((r)&7))<<4)))
#define VOFF(r,c) ROFF(r,c)

// ======================= fused pre-conversion kernel =======================
#define PRE_SPLIT_BLKS 16384
#define PRE_W_BLKS     40960
#define PRE_BT_BLKS    536

__global__ void mega_pre_kernel(
    const float4* __restrict__ hidden4, uint2* __restrict__ hh, uint2* __restrict__ hl,
    const float* __restrict__ wq, const float* __restrict__ wk,
    const float* __restrict__ wv, const float* __restrict__ wo,
    __half* __restrict__ qkvhi, __half* __restrict__ wohi,
    const float* __restrict__ bq, const float* __restrict__ bk, const float* __restrict__ bv,
    float* __restrict__ bias, float* __restrict__ ct, float* __restrict__ st)
{
    __shared__ float t[32][33];
    const int bid = blockIdx.x;
    const int tid = threadIdx.x;

    if (bid < PRE_SPLIT_BLKS) {
        int i = bid * 256 + tid;
        float4 v = hidden4[i];
        float xs[4] = {v.x, v.y, v.z, v.w};
        unsigned short hs[4], ls[4];
        #pragma unroll
        for (int j = 0; j < 4; j++) split2h(xs[j], hs[j], ls[j]);
        hh[i] = make_uint2((uint32_t)hs[0] | ((uint32_t)hs[1] << 16),
                           (uint32_t)hs[2] | ((uint32_t)hs[3] << 16));
        hl[i] = make_uint2((uint32_t)ls[0] | ((uint32_t)ls[1] << 16),
                           (uint32_t)ls[2] | ((uint32_t)ls[3] << 16));
    } else if (bid < PRE_SPLIT_BLKS + PRE_W_BLKS) {
        int v  = bid - PRE_SPLIT_BLKS;
        int k0 = (v % 128) * 32;
        int by = v / 128;
        int tx = tid & 31, ty = tid >> 5;
        const float* src; int ld, nl, n0;
        __half* dhi;
        if (by < 192) {
            n0 = by * 32;
            if (n0 < 4096)       { src = wq; ld = 4096; nl = n0; }
            else if (n0 < 5120)  { src = wk; ld = 1024; nl = n0 - 4096; }
            else                 { src = wv; ld = 1024; nl = n0 - 5120; }
            dhi = qkvhi;
        } else {
            n0 = (by - 192) * 32; src = wo; ld = DMODEL; nl = n0;
            dhi = wohi;
        }
        #pragma unroll
        for (int r = 0; r < 4; r++)
            t[ty + 8*r][tx] = src[(size_t)(k0 + ty + 8*r) * ld + nl + tx];
        __syncthreads();
        #pragma unroll
        for (int r = 0; r < 4; r++) {
            float x = t[tx][ty + 8*r];
            size_t o = (size_t)(n0 + ty + 8*r) * DMODEL + k0 + tx;
            dhi[o] = __float2half_rn(x);
        }
    } else {
        int i = (bid - PRE_SPLIT_BLKS - PRE_W_BLKS) * 256 + tid;
        if (i < QKVN) {
            bias[i] = i < 4096 ? bq[i] : (i < 5120 ? bk[i - 4096] : bv[i - 5120]);
        } else if (i < QKVN + SEQ*64) {
            int idx = i - QKVN;
            int j = idx & 63, p = idx >> 6;
            double freq = exp2(-(double)j * 0.31143075889569021);
            double ang  = (double)p * freq;
            double kq   = rint(ang * 0.15915494309189533577);
            float  a    = (float)(ang - kq * 6.28318530717958647693);
            float c, s;
            __sincosf(a, &s, &c);
            ct[idx] = c; st[idx] = s;
        }
    }
}

// ======================= fused rope + V transpose kernel =======================
#define RV_ROPE_BLKS 40960

__global__ void rope_v_kernel(const float* __restrict__ qkv, const int* __restrict__ pos,
                              const float* __restrict__ ct, const float* __restrict__ st,
                              __half* __restrict__ qhi, __half* __restrict__ qlo,
                              __half* __restrict__ khi,
                              __half* __restrict__ vth)
{
    __shared__ float t[32][33];
    const int bid = blockIdx.x;
    const int tid = threadIdx.x;

    if (bid < RV_ROPE_BLKS) {
        int idx = bid * 256 + tid;
        int j   = idx & 63;
        int hh  = (idx >> 6) % 40;
        int row = idx / (64 * 40);
        int p   = pos[row];
        float c = ct[p*64 + j], s = st[p*64 + j];
        if (hh < 32) {
            const float* ptr = qkv + (size_t)row * QKVN + hh * 128 + j;
            float x1 = ptr[0], x2 = ptr[64];
            float y1 = x1*c - x2*s;
            float y2 = x1*s + x2*c;
            size_t o = ((size_t)row * 32 + hh) * 128 + j;
            unsigned short h1,l1,h2,l2; split2h(y1,h1,l1); split2h(y2,h2,l2);
            qhi[o]    = __ushort_as_half(h1); qlo[o]    = __ushort_as_half(l1);
            qhi[o+64] = __ushort_as_half(h2); qlo[o+64] = __ushort_as_half(l2);
        } else {
            int kvh = hh - 32;
            const float* ptr = qkv + (size_t)row * QKVN + 4096 + kvh * 128 + j;
            float x1 = ptr[0], x2 = ptr[64];
            size_t o = ((size_t)row * 8 + kvh) * 128 + j;
            khi[o]    = __float2half_rn(x1*c - x2*s);
            khi[o+64] = __float2half_rn(x1*s + x2*c);
        }
    } else {
        int v  = bid - RV_ROPE_BLKS;
        int s0 = (v & 63) * 32;
        int d0 = ((v >> 6) & 3) * 32;
        int bz = v >> 8;
        int b = bz >> 3, kvh = bz & 7;
        int tx = tid & 31, ty = tid >> 5;
        #pragma unroll
        for (int r = 0; r < 4; r++)
            t[ty + 8*r][tx] = qkv[(size_t)(b*SEQ + s0 + ty + 8*r) * QKVN + 5120 + kvh*128 + d0 + tx];
        __syncthreads();
        #pragma unroll
        for (int r = 0; r < 4; r++) {
            float x = t[tx][ty + 8*r];
            size_t o = ((size_t)(b*8 + kvh) * 128 + d0 + ty + 8*r) * SEQ + s0 + tx;
            vth[o] = __float2half_rn(x);
        }
    }
}

// ======================= fp16 GEMM: persistent CTAs, 4 warps, warp tile 64x64 =======================
template<int PASSES>
__device__ __forceinline__ void g_load_stage(uint32_t sbase, int tid,
    const __half* __restrict__ Ahi, const __half* __restrict__ Alo,
    const __half* __restrict__ Bhi,
    int m0, int n0, int k0, int K)
{
    const int NOPS = PASSES + 1;
    #pragma unroll
    for (int op = 0; op < NOPS; op++) {
        const __half* src;
        int row0;
        if (op == 0)                      { src = Ahi; row0 = m0; }
        else if (PASSES == 2 && op == 1)  { src = Alo; row0 = m0; }
        else                              { src = Bhi; row0 = n0; }
        #pragma unroll
        for (int it = 0; it < 8; it++) {
            int idx = it * 128 + tid;
            int r = idx >> 3, c = idx & 7;
            const void* g = src + (size_t)(row0 + r) * K + k0 + c * 8;
            cp16(sbase + op * OPB + ROFF(r, c), g);
        }
    }
}

template<int PASSES, int STAGES>
__global__ void __launch_bounds__(128, 2) gemm_mma_kernel(
    const __half* __restrict__ Ahi, const __half* __restrict__ Alo,
    const __half* __restrict__ Bhi,
    const float* __restrict__ bias, float* __restrict__ C, int K, int ldc,
    int ntx, int nTiles)
{
    extern __shared__ char sm[];
    const uint32_t smb = smem_u32(sm);
    const uint32_t STG  = (uint32_t)(PASSES + 1) * OPB;
    const uint32_t BOFF = (uint32_t)PASSES * OPB;
    const int tid  = threadIdx.x;
    const int wid  = tid >> 5, lane = tid & 31;
    const int wm   = wid >> 1, wn = wid & 1;     // 2x2 warp grid, warp tile 64x64
    const int NC   = K / GKC;

    for (int t = blockIdx.x; t < nTiles; t += gridDim.x) {
        const int m0 = (t / ntx) * GMT;
        const int n0 = (t % ntx) * GNT;

        float acc[4][8][4];
        #pragma unroll
        for (int mt = 0; mt < 4; mt++)
            #pragma unroll
            for (int nt = 0; nt < 8; nt++)
                #pragma unroll
                for (int e = 0; e < 4; e++) acc[mt][nt][e] = 0.f;

        __syncthreads();   // protect stage buffers: all warps past previous tile's reads

        #pragma unroll
        for (int s = 0; s < STAGES - 1; s++) {
            g_load_stage<PASSES>(smb + s * STG, tid, Ahi, Alo, Bhi, m0, n0, s * GKC, K);
            CP_COMMIT();
        }

        for (int c = 0; c < NC; c++) {
            __syncthreads();
            if (c + STAGES - 1 < NC)
                g_load_stage<PASSES>(smb + ((c + STAGES - 1) % STAGES) * STG, tid,
                                     Ahi, Alo, Bhi, m0, n0, (c + STAGES - 1) * GKC, K);
            CP_COMMIT();
            CP_WAIT(STAGES - 1);
            __syncthreads();

            const uint32_t sb = smb + (c % STAGES) * STG;
            #pragma unroll
            for (int ks = 0; ks < 4; ks++) {
                uint32_t ah[4][4], al[4][4], bh[8][2];
                #pragma unroll
                for (int mt = 0; mt < 4; mt++) {
                    int r  = wm * 64 + mt * 16 + (lane & 15);
                    int cv = 2 * ks + (lane >> 4);
                    uint32_t off = ROFF(r, cv);
                    ldsm4(ah[mt][0], ah[mt][1], ah[mt][2], ah[mt][3], sb + off);
                    if (PASSES == 2)
                        ldsm4(al[mt][0], al[mt][1], al[mt][2], al[mt][3], sb + OPB + off);
                }
                #pragma unroll
                for (int np = 0; np < 4; np++) {
                    int r  = wn * 64 + np * 16 + (lane & 7) + ((lane >> 4) << 3);
                    int cv = 2 * ks + ((lane >> 3) & 1);
                    uint32_t off = ROFF(r, cv);
                    ldsm4(bh[np*2][0], bh[np*2][1], bh[np*2+1][0], bh[np*2+1][1],
                          sb + BOFF + off);
                }
                #pragma unroll
                for (int mt = 0; mt < 4; mt++)
                    #pragma unroll
                    for (int nt = 0; nt < 8; nt++) {
                        mma_fp16(acc[mt][nt], ah[mt], bh[nt]);
                        if (PASSES == 2)
                            mma_fp16(acc[mt][nt], al[mt], bh[nt]);
                    }
            }
        }

        const int tr = lane >> 2, tc = (lane & 3) * 2;
        #pragma unroll
        for (int mt = 0; mt < 4; mt++) {
            #pragma unroll
            for (int nt = 0; nt < 8; nt++) {
                int row = m0 + wm * 64 + mt * 16 + tr;
                int col = n0 + wn * 64 + nt * 8 + tc;
                float b0 = 0.f, b1 = 0.f;
                if (bias) { b0 = bias[col]; b1 = bias[col + 1]; }
                float2 v0 = make_float2(acc[mt][nt][0] + b0, acc[mt][nt][1] + b1);
                float2 v1 = make_float2(acc[mt][nt][2] + b0, acc[mt][nt][3] + b1);
                *(float2*)&C[(size_t)row * ldc + col]       = v0;
                *(float2*)&C[(size_t)(row + 8) * ldc + col] = v1;
            }
        }
    }
}

// ======================= flash attention (R14 validated, reverted) =======================
__device__ __forceinline__ void f_load_k(uint32_t skh, int tid,
    const __half* __restrict__ kh, int b, int kvh, int kt0)
{
    #pragma unroll
    for (int it = 0; it < 8; it++) {
        int i = it * 128 + tid;
        int r = i >> 4, c = i & 15;
        size_t go = ((size_t)(b*SEQ + kt0 + r) * NKV + kvh) * HDIM + c * 8;
        cp16(skh + QOFF(r, c), kh + go);
    }
}
__device__ __forceinline__ void f_load_v(uint32_t svh, int tid,
    const __half* __restrict__ vth, int b, int kvh, int kt0)
{
    #pragma unroll
    for (int it = 0; it < 8; it++) {
        int i = it * 128 + tid;
        int r = i >> 3, c = i & 7;
        size_t go = ((size_t)(b*NKV + kvh) * HDIM + r) * SEQ + kt0 + c * 8;
        cp16(svh + VOFF(r, c), vth + go);
    }
}

__global__ void __launch_bounds__(128, 2) flash_mma_kernel(
    const __half* __restrict__ qh_g, const __half* __restrict__ ql_g,
    const __half* __restrict__ kh_g,
    const __half* __restrict__ vth_g,
    __half* __restrict__ aoh)
{
    extern __shared__ char sm[];
    const uint32_t smb = smem_u32(sm);
    const uint32_t sQh = smb;
    const uint32_t sQl = smb + 16384;
    const uint32_t sKh = smb + 32768;
    const uint32_t sVh = smb + 49152;

    const int tid  = threadIdx.x;
    const int w    = tid >> 5, lane = tid & 31;
    const int qt0  = (int)(gridDim.x - 1 - blockIdx.x) * FBQ;
    const int h    = blockIdx.y;
    const int b    = blockIdx.z;
    const int kvh  = h >> 2;
    const int nt   = qt0 / FBK + 1;

    #pragma unroll
    for (int it = 0; it < 8; it++) {
        int i = it * 128 + tid;
        int r = i >> 4, c = i & 15;
        size_t go = ((size_t)(b*SEQ + qt0 + r) * NH + h) * HDIM + c * 8;
        cp16(sQh + QOFF(r, c), qh_g + go);
        cp16(sQl + QOFF(r, c), ql_g + go);
    }
    CP_COMMIT();
    f_load_k(sKh, tid, kh_g, b, kvh, 0);
    CP_COMMIT();
    f_load_v(sVh, tid, vth_g, b, kvh, 0);
    CP_COMMIT();

    float O[16][4];
    #pragma unroll
    for (int i = 0; i < 16; i++)
        #pragma unroll
        for (int e = 0; e < 4; e++) O[i][e] = 0.f;
    float l0 = 0.f, l1 = 0.f;

    for (int kt = 0; kt < nt; kt++) {
        CP_WAIT(1);
        __syncthreads();

        float s[8][4];
        #pragma unroll
        for (int i = 0; i < 8; i++)
            #pragma unroll
            for (int e = 0; e < 4; e++) s[i][e] = 0.f;

        #pragma unroll
        for (int ks = 0; ks < 8; ks++) {
            uint32_t ah[4], al[4];
            uint32_t qoff = QOFF(w*16 + (lane & 15), 2*ks + (lane >> 4));
            ldsm4(ah[0], ah[1], ah[2], ah[3], sQh + qoff);
            ldsm4(al[0], al[1], al[2], al[3], sQl + qoff);
            uint32_t bh[8][2];
            #pragma unroll
            for (int np = 0; np < 4; np++) {
                uint32_t boff = QOFF(np*16 + (lane & 7) + ((lane >> 4) << 3),
                                     2*ks + ((lane >> 3) & 1));
                ldsm4(bh[np*2][0], bh[np*2][1], bh[np*2+1][0], bh[np*2+1][1], sKh + boff);
            }
            #pragma unroll
            for (int ntl = 0; ntl < 8; ntl++) {
                mma_fp16(s[ntl], ah, bh[ntl]);
                mma_fp16(s[ntl], al, bh[ntl]);
            }
        }

        if (kt == nt - 1) {
            int r0 = qt0 + w*16 + (lane >> 2);
            int c0 = kt*FBK + (lane & 3)*2;
            #pragma unroll
            for (int ntl = 0; ntl < 8; ntl++) {
                int cb = c0 + ntl*8;
                if (cb     > r0)     s[ntl][0] = -1e30f;
                if (cb + 1 > r0)     s[ntl][1] = -1e30f;
                if (cb     > r0 + 8) s[ntl][2] = -1e30f;
                if (cb + 1 > r0 + 8) s[ntl][3] = -1e30f;
            }
        }

        __syncthreads();
        if (kt + 1 < nt)
            f_load_k(sKh, tid, kh_g, b, kvh, (kt + 1) * FBK);
        CP_COMMIT();

        float rs0 = 0.f, rs1 = 0.f;
        #pragma unroll
        for (int ntl = 0; ntl < 8; ntl++) {
            s[ntl][0] = __expf(s[ntl][0] * SCALE);
            s[ntl][1] = __expf(s[ntl][1] * SCALE);
            s[ntl][2] = __expf(s[ntl][2] * SCALE);
            s[ntl][3] = __expf(s[ntl][3] * SCALE);
            rs0 += s[ntl][0] + s[ntl][1];
            rs1 += s[ntl][2] + s[ntl][3];
        }
        rs0 += __shfl_xor_sync(0xffffffffu, rs0, 1);
        rs0 += __shfl_xor_sync(0xffffffffu, rs0, 2);
        rs1 += __shfl_xor_sync(0xffffffffu, rs1, 1);
        rs1 += __shfl_xor_sync(0xffffffffu, rs1, 2);
        l0 += rs0; l1 += rs1;

        CP_WAIT(1);
        __syncthreads();

        #pragma unroll
        for (int kk = 0; kk < 4; kk++) {
            uint32_t ph[4];
            ph[0] = pack2h(s[2*kk][0],   s[2*kk][1]);
            ph[1] = pack2h(s[2*kk][2],   s[2*kk][3]);
            ph[2] = pack2h(s[2*kk+1][0], s[2*kk+1][1]);
            ph[3] = pack2h(s[2*kk+1][2], s[2*kk+1][3]);
            #pragma unroll
            for (int np = 0; np < 8; np++) {
                uint32_t vh0[2], vh1[2];
                uint32_t voff = VOFF(np*16 + (lane & 7) + ((lane >> 4) << 3),
                                     2*kk + ((lane >> 3) & 1));
                ldsm4(vh0[0], vh0[1], vh1[0], vh1[1], sVh + voff);
                mma_fp16(O[np*2],   ph, vh0);
                mma_fp16(O[np*2+1], ph, vh1);
            }
        }

        __syncthreads();
        if (kt + 1 < nt)
            f_load_v(sVh, tid, vth_g, b, kvh, (kt + 1) * FBK);
        CP_COMMIT();
    }

    float inv0 = 1.f / l0, inv1 = 1.f / l1;
    int r0 = qt0 + w*16 + (lane >> 2);
    size_t base0 = ((size_t)(b*SEQ + r0)     * NH + h) * HDIM;
    size_t base1 = ((size_t)(b*SEQ + r0 + 8) * NH + h) * HDIM;
    #pragma unroll
    for (int i = 0; i < 16; i++) {
        int d = i*8 + (lane & 3)*2;
        *(uint32_t*)(aoh + base0 + d) = pack2h(O[i][0]*inv0, O[i][1]*inv0);
        *(uint32_t*)(aoh + base1 + d) = pack2h(O[i][2]*inv1, O[i][3]*inv1);
    }
}

// ======================= Launch =======================
extern "C" void kernel_launch(void* const* d_in, const int* in_sizes, int n_in,
                              void* d_out, int out_size)
{
    const float* hidden = (const float*)d_in[0];
    const int*   pos    = (const int*)  d_in[1];
    const float* wq     = (const float*)d_in[2];
    const float* bq     = (const float*)d_in[3];
    const float* wk     = (const float*)d_in[4];
    const float* bk     = (const float*)d_in[5];
    const float* wv     = (const float*)d_in[6];
    const float* bv     = (const float*)d_in[7];
    const float* wo     = (const float*)d_in[8];
    float* out = (float*)d_out;

    __half *hh, *hl, *qwh, *owh, *qhi, *qlo, *khi, *vth, *aoh;
    float *qkv, *bias, *ct, *st;
    cudaGetSymbolAddress((void**)&hh,  g_hid_hi);
    cudaGetSymbolAddress((void**)&hl,  g_hid_lo);
    cudaGetSymbolAddress((void**)&qwh, g_wqkv_hi);
    cudaGetSymbolAddress((void**)&owh, g_wo_hi);
    cudaGetSymbolAddress((void**)&qhi, g_q_hi);
    cudaGetSymbolAddress((void**)&qlo, g_q_lo);
    cudaGetSymbolAddress((void**)&khi, g_k_hi);
    cudaGetSymbolAddress((void**)&vth, g_vt_hi);
    cudaGetSymbolAddress((void**)&aoh, g_ao_hi);
    cudaGetSymbolAddress((void**)&qkv, g_qkv);
    cudaGetSymbolAddress((void**)&bias,g_bias);
    cudaGetSymbolAddress((void**)&ct,  g_cos);
    cudaGetSymbolAddress((void**)&st,  g_sin);

    cudaFuncSetAttribute((const void*)gemm_mma_kernel<2,2>, cudaFuncAttributeMaxDynamicSharedMemorySize, 2*3*OPB);
    cudaFuncSetAttribute((const void*)gemm_mma_kernel<1,3>, cudaFuncAttributeMaxDynamicSharedMemorySize, 3*2*OPB);
    cudaFuncSetAttribute((const void*)flash_mma_kernel, cudaFuncAttributeMaxDynamicSharedMemorySize, FLASH_SMEM);

    mega_pre_kernel<<<PRE_SPLIT_BLKS + PRE_W_BLKS + PRE_BT_BLKS, 256>>>(
        (const float4*)hidden, (uint2*)hh, (uint2*)hl,
        wq, wk, wv, wo, qwh, owh, bq, bk, bv, bias, ct, st);

    // gemm1: 48 x 32 = 1536 tiles, persistent over 296 CTAs
    {
        int ntx = QKVN / GNT, nTiles = ntx * (MTOT / GMT);
        gemm_mma_kernel<2,2><<<PERSIST_CTAS, 128, 2*3*OPB>>>(
            hh, hl, qwh, bias, qkv, DMODEL, QKVN, ntx, nTiles);
    }

    rope_v_kernel<<<RV_ROPE_BLKS + 4096, 256>>>(qkv, pos, ct, st, qhi, qlo, khi, vth);

    flash_mma_kernel<<<dim3(SEQ/FBQ, NH, BATCH), 128, FLASH_SMEM>>>(
        qhi, qlo, khi, vth, aoh);

    // gemm2: 32 x 32 = 1024 tiles, persistent over 296 CTAs
    {
        int ntx = DMODEL / GNT, nTiles = ntx * (MTOT / GMT);
        gemm_mma_kernel<1,3><<<PERSIST_CTAS, 128, 3*2*OPB>>>(
            aoh, nullptr, owh, nullptr, out, DMODEL, DMODEL, ntx, nTiles);
    }
}

// round 17
// speedup vs baseline: 1.1344x; 1.1344x over previous
#include <cuda_runtime.h>
#include <cuda_bf16.h>
#include <cuda_fp16.h>
#include <cstdint>
#include <math.h>

// Problem constants
#define BATCH  2
#define SEQ    2048
#define DMODEL 4096
#define NH     32
#define NKV    8
#define HDIM   128
#define MTOT   (BATCH*SEQ)
#define QKVN   6144
#define SCALE  0.08838834764831843f   // 1/sqrt(128)

// GEMM tiling: 128x128 CTA tile, 4 warps (2x2), warp tile 64x64, GKC=64 (R14 validated)
#define GMT 128
#define GNT 128
#define GKC 64
#define OPB (128*GKC*2)                // 16KB per operand tile

// flash tiling (R14 validated)
#define FBQ 64
#define FBK 64
#define FLASH_SMEM 65536

// -------- scratch --------
__device__ __align__(16) __half g_hid_hi [(size_t)MTOT*DMODEL];
__device__ __align__(16) __half g_hid_lo [(size_t)MTOT*DMODEL];
__device__ __align__(16) __half g_wqkv_hi[(size_t)QKVN*DMODEL];
__device__ __align__(16) __half g_wo_hi  [(size_t)DMODEL*DMODEL];
__device__ __align__(16) float g_qkv [(size_t)MTOT*QKVN];
__device__ __align__(16) __half g_q_hi [(size_t)MTOT*NH*HDIM];
__device__ __align__(16) __half g_q_lo [(size_t)MTOT*NH*HDIM];
__device__ __align__(16) __half g_k_hi [(size_t)MTOT*NKV*HDIM];
__device__ __align__(16) __half g_vt_hi[(size_t)BATCH*NKV*HDIM*SEQ];
__device__ __align__(16) __half g_ao_hi[(size_t)MTOT*DMODEL];
__device__ float g_bias[QKVN];
__device__ float g_cos[SEQ*64];
__device__ float g_sin[SEQ*64];

// ======================= helpers =======================
__device__ __forceinline__ uint32_t smem_u32(const void* p) {
    uint32_t a;
    asm("{ .reg .u64 t; cvta.to.shared.u64 t, %1; cvt.u32.u64 %0, t; }" : "=r"(a) : "l"(p));
    return a;
}
__device__ __forceinline__ void cp16(uint32_t s, const void* g) {
    asm volatile("cp.async.cg.shared.global [%0], [%1], 16;" :: "r"(s), "l"(g));
}
#define CP_COMMIT()  asm volatile("cp.async.commit_group;" ::: "memory")
#define CP_WAIT(n)   asm volatile("cp.async.wait_group %0;" :: "n"(n) : "memory")

__device__ __forceinline__ void ldsm4(uint32_t& r0, uint32_t& r1, uint32_t& r2, uint32_t& r3,
                                      uint32_t a) {
    asm volatile("ldmatrix.sync.aligned.m8n8.x4.shared.b16 {%0,%1,%2,%3}, [%4];"
        : "=r"(r0), "=r"(r1), "=r"(r2), "=r"(r3) : "r"(a));
}
__device__ __forceinline__ void mma_fp16(float* c, const uint32_t* a, const uint32_t* b) {
    asm volatile("mma.sync.aligned.m16n8k16.row.col.f32.f16.f16.f32 "
        "{%0,%1,%2,%3}, {%4,%5,%6,%7}, {%8,%9}, {%0,%1,%2,%3};"
        : "+f"(c[0]), "+f"(c[1]), "+f"(c[2]), "+f"(c[3])
        : "r"(a[0]), "r"(a[1]), "r"(a[2]), "r"(a[3]), "r"(b[0]), "r"(b[1]));
}
__device__ __forceinline__ void split2h(float x, unsigned short& h, unsigned short& l) {
    __half hb = __float2half_rn(x);
    float hf = __half2float(hb);
    __half lb = __float2half_rn(x - hf);
    h = __half_as_ushort(hb);
    l = __half_as_ushort(lb);
}
__device__ __forceinline__ uint32_t pack2h(float x0, float x1) {
    return (uint32_t)__half_as_ushort(__float2half_rn(x0)) |
           ((uint32_t)__half_as_ushort(__float2half_rn(x1)) << 16);
}
#define ROFF(r,c) ((uint32_t)((r)*128 + (((c) ^ ((r)&7))<<4)))
#define QOFF(r,c) ((uint32_t)((r)*256 + (((c) ^ ((r)&7))<<4)))
#define VOFF(r,c) ROFF(r,c)

// ======================= fused pre-conversion kernel =======================
#define PRE_SPLIT_BLKS 16384
#define PRE_W_BLKS     40960
#define PRE_BT_BLKS    536

__global__ void mega_pre_kernel(
    const float4* __restrict__ hidden4, uint2* __restrict__ hh, uint2* __restrict__ hl,
    const float* __restrict__ wq, const float* __restrict__ wk,
    const float* __restrict__ wv, const float* __restrict__ wo,
    __half* __restrict__ qkvhi, __half* __restrict__ wohi,
    const float* __restrict__ bq, const float* __restrict__ bk, const float* __restrict__ bv,
    float* __restrict__ bias, float* __restrict__ ct, float* __restrict__ st)
{
    __shared__ float t[32][33];
    const int bid = blockIdx.x;
    const int tid = threadIdx.x;

    if (bid < PRE_SPLIT_BLKS) {
        int i = bid * 256 + tid;
        float4 v = hidden4[i];
        float xs[4] = {v.x, v.y, v.z, v.w};
        unsigned short hs[4], ls[4];
        #pragma unroll
        for (int j = 0; j < 4; j++) split2h(xs[j], hs[j], ls[j]);
        hh[i] = make_uint2((uint32_t)hs[0] | ((uint32_t)hs[1] << 16),
                           (uint32_t)hs[2] | ((uint32_t)hs[3] << 16));
        hl[i] = make_uint2((uint32_t)ls[0] | ((uint32_t)ls[1] << 16),
                           (uint32_t)ls[2] | ((uint32_t)ls[3] << 16));
    } else if (bid < PRE_SPLIT_BLKS + PRE_W_BLKS) {
        int v  = bid - PRE_SPLIT_BLKS;
        int k0 = (v % 128) * 32;
        int by = v / 128;
        int tx = tid & 31, ty = tid >> 5;
        const float* src; int ld, nl, n0;
        __half* dhi;
        if (by < 192) {
            n0 = by * 32;
            if (n0 < 4096)       { src = wq; ld = 4096; nl = n0; }
            else if (n0 < 5120)  { src = wk; ld = 1024; nl = n0 - 4096; }
            else                 { src = wv; ld = 1024; nl = n0 - 5120; }
            dhi = qkvhi;
        } else {
            n0 = (by - 192) * 32; src = wo; ld = DMODEL; nl = n0;
            dhi = wohi;
        }
        #pragma unroll
        for (int r = 0; r < 4; r++)
            t[ty + 8*r][tx] = src[(size_t)(k0 + ty + 8*r) * ld + nl + tx];
        __syncthreads();
        #pragma unroll
        for (int r = 0; r < 4; r++) {
            float x = t[tx][ty + 8*r];
            size_t o = (size_t)(n0 + ty + 8*r) * DMODEL + k0 + tx;
            dhi[o] = __float2half_rn(x);
        }
    } else {
        int i = (bid - PRE_SPLIT_BLKS - PRE_W_BLKS) * 256 + tid;
        if (i < QKVN) {
            bias[i] = i < 4096 ? bq[i] : (i < 5120 ? bk[i - 4096] : bv[i - 5120]);
        } else if (i < QKVN + SEQ*64) {
            int idx = i - QKVN;
            int j = idx & 63, p = idx >> 6;
            double freq = exp2(-(double)j * 0.31143075889569021);
            double ang  = (double)p * freq;
            double kq   = rint(ang * 0.15915494309189533577);
            float  a    = (float)(ang - kq * 6.28318530717958647693);
            float c, s;
            __sincosf(a, &s, &c);
            ct[idx] = c; st[idx] = s;
        }
    }
}

// ======================= fused rope + V transpose kernel =======================
#define RV_ROPE_BLKS 40960

__global__ void rope_v_kernel(const float* __restrict__ qkv, const int* __restrict__ pos,
                              const float* __restrict__ ct, const float* __restrict__ st,
                              __half* __restrict__ qhi, __half* __restrict__ qlo,
                              __half* __restrict__ khi,
                              __half* __restrict__ vth)
{
    __shared__ float t[32][33];
    const int bid = blockIdx.x;
    const int tid = threadIdx.x;

    if (bid < RV_ROPE_BLKS) {
        int idx = bid * 256 + tid;
        int j   = idx & 63;
        int hh  = (idx >> 6) % 40;
        int row = idx / (64 * 40);
        int p   = pos[row];
        float c = ct[p*64 + j], s = st[p*64 + j];
        if (hh < 32) {
            const float* ptr = qkv + (size_t)row * QKVN + hh * 128 + j;
            float x1 = ptr[0], x2 = ptr[64];
            float y1 = x1*c - x2*s;
            float y2 = x1*s + x2*c;
            size_t o = ((size_t)row * 32 + hh) * 128 + j;
            unsigned short h1,l1,h2,l2; split2h(y1,h1,l1); split2h(y2,h2,l2);
            qhi[o]    = __ushort_as_half(h1); qlo[o]    = __ushort_as_half(l1);
            qhi[o+64] = __ushort_as_half(h2); qlo[o+64] = __ushort_as_half(l2);
        } else {
            int kvh = hh - 32;
            const float* ptr = qkv + (size_t)row * QKVN + 4096 + kvh * 128 + j;
            float x1 = ptr[0], x2 = ptr[64];
            size_t o = ((size_t)row * 8 + kvh) * 128 + j;
            khi[o]    = __float2half_rn(x1*c - x2*s);
            khi[o+64] = __float2half_rn(x1*s + x2*c);
        }
    } else {
        int v  = bid - RV_ROPE_BLKS;
        int s0 = (v & 63) * 32;
        int d0 = ((v >> 6) & 3) * 32;
        int bz = v >> 8;
        int b = bz >> 3, kvh = bz & 7;
        int tx = tid & 31, ty = tid >> 5;
        #pragma unroll
        for (int r = 0; r < 4; r++)
            t[ty + 8*r][tx] = qkv[(size_t)(b*SEQ + s0 + ty + 8*r) * QKVN + 5120 + kvh*128 + d0 + tx];
        __syncthreads();
        #pragma unroll
        for (int r = 0; r < 4; r++) {
            float x = t[tx][ty + 8*r];
            size_t o = ((size_t)(b*8 + kvh) * 128 + d0 + ty + 8*r) * SEQ + s0 + tx;
            vth[o] = __float2half_rn(x);
        }
    }
}

// ======================= fp16 GEMM: 4 warps, warp tile 64x64, GKC=64 (R14) =======================
template<int PASSES>
__device__ __forceinline__ void g_load_stage(uint32_t sbase, int tid,
    const __half* __restrict__ Ahi, const __half* __restrict__ Alo,
    const __half* __restrict__ Bhi,
    int m0, int n0, int k0, int K)
{
    const int NOPS = PASSES + 1;
    #pragma unroll
    for (int op = 0; op < NOPS; op++) {
        const __half* src;
        int row0;
        if (op == 0)                      { src = Ahi; row0 = m0; }
        else if (PASSES == 2 && op == 1)  { src = Alo; row0 = m0; }
        else                              { src = Bhi; row0 = n0; }
        #pragma unroll
        for (int it = 0; it < 8; it++) {
            int idx = it * 128 + tid;
            int r = idx >> 3, c = idx & 7;
            const void* g = src + (size_t)(row0 + r) * K + k0 + c * 8;
            cp16(sbase + op * OPB + ROFF(r, c), g);
        }
    }
}

template<int PASSES, int STAGES>
__global__ void __launch_bounds__(128, 2) gemm_mma_kernel(
    const __half* __restrict__ Ahi, const __half* __restrict__ Alo,
    const __half* __restrict__ Bhi,
    const float* __restrict__ bias, float* __restrict__ C, int K, int ldc)
{
    extern __shared__ char sm[];
    const uint32_t smb = smem_u32(sm);
    const uint32_t STG  = (uint32_t)(PASSES + 1) * OPB;
    const uint32_t BOFF = (uint32_t)PASSES * OPB;
    const int tid  = threadIdx.x;
    const int wid  = tid >> 5, lane = tid & 31;
    const int wm   = wid >> 1, wn = wid & 1;
    const int m0   = blockIdx.y * GMT;
    const int n0   = blockIdx.x * GNT;
    const int NC   = K / GKC;

    float acc[4][8][4];
    #pragma unroll
    for (int mt = 0; mt < 4; mt++)
        #pragma unroll
        for (int nt = 0; nt < 8; nt++)
            #pragma unroll
            for (int e = 0; e < 4; e++) acc[mt][nt][e] = 0.f;

    #pragma unroll
    for (int s = 0; s < STAGES - 1; s++) {
        g_load_stage<PASSES>(smb + s * STG, tid, Ahi, Alo, Bhi, m0, n0, s * GKC, K);
        CP_COMMIT();
    }

    for (int c = 0; c < NC; c++) {
        __syncthreads();
        if (c + STAGES - 1 < NC)
            g_load_stage<PASSES>(smb + ((c + STAGES - 1) % STAGES) * STG, tid,
                                 Ahi, Alo, Bhi, m0, n0, (c + STAGES - 1) * GKC, K);
        CP_COMMIT();
        CP_WAIT(STAGES - 1);
        __syncthreads();

        const uint32_t sb = smb + (c % STAGES) * STG;
        #pragma unroll
        for (int ks = 0; ks < 4; ks++) {
            uint32_t ah[4][4], al[4][4], bh[8][2];
            #pragma unroll
            for (int mt = 0; mt < 4; mt++) {
                int r  = wm * 64 + mt * 16 + (lane & 15);
                int cv = 2 * ks + (lane >> 4);
                uint32_t off = ROFF(r, cv);
                ldsm4(ah[mt][0], ah[mt][1], ah[mt][2], ah[mt][3], sb + off);
                if (PASSES == 2)
                    ldsm4(al[mt][0], al[mt][1], al[mt][2], al[mt][3], sb + OPB + off);
            }
            #pragma unroll
            for (int np = 0; np < 4; np++) {
                int r  = wn * 64 + np * 16 + (lane & 7) + ((lane >> 4) << 3);
                int cv = 2 * ks + ((lane >> 3) & 1);
                uint32_t off = ROFF(r, cv);
                ldsm4(bh[np*2][0], bh[np*2][1], bh[np*2+1][0], bh[np*2+1][1],
                      sb + BOFF + off);
            }
            #pragma unroll
            for (int mt = 0; mt < 4; mt++)
                #pragma unroll
                for (int nt = 0; nt < 8; nt++) {
                    mma_fp16(acc[mt][nt], ah[mt], bh[nt]);
                    if (PASSES == 2)
                        mma_fp16(acc[mt][nt], al[mt], bh[nt]);
                }
        }
    }

    const int tr = lane >> 2, tc = (lane & 3) * 2;
    #pragma unroll
    for (int mt = 0; mt < 4; mt++) {
        #pragma unroll
        for (int nt = 0; nt < 8; nt++) {
            int row = m0 + wm * 64 + mt * 16 + tr;
            int col = n0 + wn * 64 + nt * 8 + tc;
            float b0 = 0.f, b1 = 0.f;
            if (bias) { b0 = bias[col]; b1 = bias[col + 1]; }
            float2 v0 = make_float2(acc[mt][nt][0] + b0, acc[mt][nt][1] + b1);
            float2 v1 = make_float2(acc[mt][nt][2] + b0, acc[mt][nt][3] + b1);
            *(float2*)&C[(size_t)row * ldc + col]       = v0;
            *(float2*)&C[(size_t)(row + 8) * ldc + col] = v1;
        }
    }
}

// ======================= flash attention (R14 validated) =======================
__device__ __forceinline__ void f_load_k(uint32_t skh, int tid,
    const __half* __restrict__ kh, int b, int kvh, int kt0)
{
    #pragma unroll
    for (int it = 0; it < 8; it++) {
        int i = it * 128 + tid;
        int r = i >> 4, c = i & 15;
        size_t go = ((size_t)(b*SEQ + kt0 + r) * NKV + kvh) * HDIM + c * 8;
        cp16(skh + QOFF(r, c), kh + go);
    }
}
__device__ __forceinline__ void f_load_v(uint32_t svh, int tid,
    const __half* __restrict__ vth, int b, int kvh, int kt0)
{
    #pragma unroll
    for (int it = 0; it < 8; it++) {
        int i = it * 128 + tid;
        int r = i >> 3, c = i & 7;
        size_t go = ((size_t)(b*NKV + kvh) * HDIM + r) * SEQ + kt0 + c * 8;
        cp16(svh + VOFF(r, c), vth + go);
    }
}

__global__ void __launch_bounds__(128, 2) flash_mma_kernel(
    const __half* __restrict__ qh_g, const __half* __restrict__ ql_g,
    const __half* __restrict__ kh_g,
    const __half* __restrict__ vth_g,
    __half* __restrict__ aoh)
{
    extern __shared__ char sm[];
    const uint32_t smb = smem_u32(sm);
    const uint32_t sQh = smb;
    const uint32_t sQl = smb + 16384;
    const uint32_t sKh = smb + 32768;
    const uint32_t sVh = smb + 49152;

    const int tid  = threadIdx.x;
    const int w    = tid >> 5, lane = tid & 31;
    const int qt0  = (int)(gridDim.x - 1 - blockIdx.x) * FBQ;
    const int h    = blockIdx.y;
    const int b    = blockIdx.z;
    const int kvh  = h >> 2;
    const int nt   = qt0 / FBK + 1;

    #pragma unroll
    for (int it = 0; it < 8; it++) {
        int i = it * 128 + tid;
        int r = i >> 4, c = i & 15;
        size_t go = ((size_t)(b*SEQ + qt0 + r) * NH + h) * HDIM + c * 8;
        cp16(sQh + QOFF(r, c), qh_g + go);
        cp16(sQl + QOFF(r, c), ql_g + go);
    }
    CP_COMMIT();
    f_load_k(sKh, tid, kh_g, b, kvh, 0);
    CP_COMMIT();
    f_load_v(sVh, tid, vth_g, b, kvh, 0);
    CP_COMMIT();

    float O[16][4];
    #pragma unroll
    for (int i = 0; i < 16; i++)
        #pragma unroll
        for (int e = 0; e < 4; e++) O[i][e] = 0.f;
    float l0 = 0.f, l1 = 0.f;

    for (int kt = 0; kt < nt; kt++) {
        CP_WAIT(1);
        __syncthreads();

        float s[8][4];
        #pragma unroll
        for (int i = 0; i < 8; i++)
            #pragma unroll
            for (int e = 0; e < 4; e++) s[i][e] = 0.f;

        #pragma unroll
        for (int ks = 0; ks < 8; ks++) {
            uint32_t ah[4], al[4];
            uint32_t qoff = QOFF(w*16 + (lane & 15), 2*ks + (lane >> 4));
            ldsm4(ah[0], ah[1], ah[2], ah[3], sQh + qoff);
            ldsm4(al[0], al[1], al[2], al[3], sQl + qoff);
            uint32_t bh[8][2];
            #pragma unroll
            for (int np = 0; np < 4; np++) {
                uint32_t boff = QOFF(np*16 + (lane & 7) + ((lane >> 4) << 3),
                                     2*ks + ((lane >> 3) & 1));
                ldsm4(bh[np*2][0], bh[np*2][1], bh[np*2+1][0], bh[np*2+1][1], sKh + boff);
            }
            #pragma unroll
            for (int ntl = 0; ntl < 8; ntl++) {
                mma_fp16(s[ntl], ah, bh[ntl]);
                mma_fp16(s[ntl], al, bh[ntl]);
            }
        }

        if (kt == nt - 1) {
            int r0 = qt0 + w*16 + (lane >> 2);
            int c0 = kt*FBK + (lane & 3)*2;
            #pragma unroll
            for (int ntl = 0; ntl < 8; ntl++) {
                int cb = c0 + ntl*8;
                if (cb     > r0)     s[ntl][0] = -1e30f;
                if (cb + 1 > r0)     s[ntl][1] = -1e30f;
                if (cb     > r0 + 8) s[ntl][2] = -1e30f;
                if (cb + 1 > r0 + 8) s[ntl][3] = -1e30f;
            }
        }

        __syncthreads();
        if (kt + 1 < nt)
            f_load_k(sKh, tid, kh_g, b, kvh, (kt + 1) * FBK);
        CP_COMMIT();

        float rs0 = 0.f, rs1 = 0.f;
        #pragma unroll
        for (int ntl = 0; ntl < 8; ntl++) {
            s[ntl][0] = __expf(s[ntl][0] * SCALE);
            s[ntl][1] = __expf(s[ntl][1] * SCALE);
            s[ntl][2] = __expf(s[ntl][2] * SCALE);
            s[ntl][3] = __expf(s[ntl][3] * SCALE);
            rs0 += s[ntl][0] + s[ntl][1];
            rs1 += s[ntl][2] + s[ntl][3];
        }
        rs0 += __shfl_xor_sync(0xffffffffu, rs0, 1);
        rs0 += __shfl_xor_sync(0xffffffffu, rs0, 2);
        rs1 += __shfl_xor_sync(0xffffffffu, rs1, 1);
        rs1 += __shfl_xor_sync(0xffffffffu, rs1, 2);
        l0 += rs0; l1 += rs1;

        CP_WAIT(1);
        __syncthreads();

        #pragma unroll
        for (int kk = 0; kk < 4; kk++) {
            uint32_t ph[4];
            ph[0] = pack2h(s[2*kk][0],   s[2*kk][1]);
            ph[1] = pack2h(s[2*kk][2],   s[2*kk][3]);
            ph[2] = pack2h(s[2*kk+1][0], s[2*kk+1][1]);
            ph[3] = pack2h(s[2*kk+1][2], s[2*kk+1][3]);
            #pragma unroll
            for (int np = 0; np < 8; np++) {
                uint32_t vh0[2], vh1[2];
                uint32_t voff = VOFF(np*16 + (lane & 7) + ((lane >> 4) << 3),
                                     2*kk + ((lane >> 3) & 1));
                ldsm4(vh0[0], vh0[1], vh1[0], vh1[1], sVh + voff);
                mma_fp16(O[np*2],   ph, vh0);
                mma_fp16(O[np*2+1], ph, vh1);
            }
        }

        __syncthreads();
        if (kt + 1 < nt)
            f_load_v(sVh, tid, vth_g, b, kvh, (kt + 1) * FBK);
        CP_COMMIT();
    }

    float inv0 = 1.f / l0, inv1 = 1.f / l1;
    int r0 = qt0 + w*16 + (lane >> 2);
    size_t base0 = ((size_t)(b*SEQ + r0)     * NH + h) * HDIM;
    size_t base1 = ((size_t)(b*SEQ + r0 + 8) * NH + h) * HDIM;
    #pragma unroll
    for (int i = 0; i < 16; i++) {
        int d = i*8 + (lane & 3)*2;
        *(uint32_t*)(aoh + base0 + d) = pack2h(O[i][0]*inv0, O[i][1]*inv0);
        *(uint32_t*)(aoh + base1 + d) = pack2h(O[i][2]*inv1, O[i][3]*inv1);
    }
}

// ======================= Launch =======================
extern "C" void kernel_launch(void* const* d_in, const int* in_sizes, int n_in,
                              void* d_out, int out_size)
{
    const float* hidden = (const float*)d_in[0];
    const int*   pos    = (const int*)  d_in[1];
    const float* wq     = (const float*)d_in[2];
    const float* bq     = (const float*)d_in[3];
    const float* wk     = (const float*)d_in[4];
    const float* bk     = (const float*)d_in[5];
    const float* wv     = (const float*)d_in[6];
    const float* bv     = (const float*)d_in[7];
    const float* wo     = (const float*)d_in[8];
    float* out = (float*)d_out;

    __half *hh, *hl, *qwh, *owh, *qhi, *qlo, *khi, *vth, *aoh;
    float *qkv, *bias, *ct, *st;
    cudaGetSymbolAddress((void**)&hh,  g_hid_hi);
    cudaGetSymbolAddress((void**)&hl,  g_hid_lo);
    cudaGetSymbolAddress((void**)&qwh, g_wqkv_hi);
    cudaGetSymbolAddress((void**)&owh, g_wo_hi);
    cudaGetSymbolAddress((void**)&qhi, g_q_hi);
    cudaGetSymbolAddress((void**)&qlo, g_q_lo);
    cudaGetSymbolAddress((void**)&khi, g_k_hi);
    cudaGetSymbolAddress((void**)&vth, g_vt_hi);
    cudaGetSymbolAddress((void**)&aoh, g_ao_hi);
    cudaGetSymbolAddress((void**)&qkv, g_qkv);
    cudaGetSymbolAddress((void**)&bias,g_bias);
    cudaGetSymbolAddress((void**)&ct,  g_cos);
    cudaGetSymbolAddress((void**)&st,  g_sin);

    cudaFuncSetAttribute((const void*)gemm_mma_kernel<2,2>, cudaFuncAttributeMaxDynamicSharedMemorySize, 2*3*OPB);
    cudaFuncSetAttribute((const void*)gemm_mma_kernel<1,3>, cudaFuncAttributeMaxDynamicSharedMemorySize, 3*2*OPB);
    cudaFuncSetAttribute((const void*)flash_mma_kernel, cudaFuncAttributeMaxDynamicSharedMemorySize, FLASH_SMEM);

    mega_pre_kernel<<<PRE_SPLIT_BLKS + PRE_W_BLKS + PRE_BT_BLKS, 256>>>(
        (const float4*)hidden, (uint2*)hh, (uint2*)hl,
        wq, wk, wv, wo, qwh, owh, bq, bk, bv, bias, ct, st);

    // q projection: N in [0,4096), 2-pass (precision anchor for logits via Q hi/lo)
    gemm_mma_kernel<2,2><<<dim3(DMODEL/GNT, MTOT/GMT), 128, 2*3*OPB>>>(
        hh, hl, qwh, bias, qkv, DMODEL, QKVN);
    // k,v projection: N in [4096,6144), 1-pass (k,v are rounded to fp16 downstream anyway)
    gemm_mma_kernel<1,3><<<dim3((QKVN-DMODEL)/GNT, MTOT/GMT), 128, 3*2*OPB>>>(
        hh, nullptr, qwh + (size_t)DMODEL*DMODEL, bias + DMODEL,
        qkv + DMODEL, DMODEL, QKVN);

    rope_v_kernel<<<RV_ROPE_BLKS + 4096, 256>>>(qkv, pos, ct, st, qhi, qlo, khi, vth);

    flash_mma_kernel<<<dim3(SEQ/FBQ, NH, BATCH), 128, FLASH_SMEM>>>(
        qhi, qlo, khi, vth, aoh);

    gemm_mma_kernel<1,3><<<dim3(DMODEL/GNT, MTOT/GMT), 128, 3*2*OPB>>>(
        aoh, nullptr, owh, nullptr, out, DMODEL, DMODEL);
}